// round 1
// baseline (speedup 1.0000x reference)
#include <cuda_runtime.h>

// ST-BIF IF neuron, multistep scan over T=16.
// One thread owns 4 spatial elements (float4) and carries state (q, acc)
// in registers across the 16 timesteps. Pure streaming: 616MB in, 616MB out.

#define T_STEPS 16
#define POS_MAX 7
#define NEG_MIN (-8)

__global__ void __launch_bounds__(256) ifneuron_kernel(
    const float* __restrict__ x,
    const float* __restrict__ qth_ptr,
    float* __restrict__ out,
    int S)   // spatial size (B*N*D), multiple of 4
{
    int idx = (blockIdx.x * blockDim.x + threadIdx.x) * 4;
    if (idx >= S) return;

    const float qth = __ldg(qth_ptr);

    float q0 = 0.5f, q1 = 0.5f, q2 = 0.5f, q3 = 0.5f;
    int a0 = 0, a1 = 0, a2 = 0, a3 = 0;

    #pragma unroll
    for (int t = 0; t < T_STEPS; t++) {
        float4 xv = *reinterpret_cast<const float4*>(x + (size_t)t * S + idx);
        float4 ov;

        // element 0
        {
            q0 += xv.x / qth;                       // IEEE div matches jnp
            bool sp = (q0 - 1.0f >= 0.0f) && (a0 < POS_MAX);
            bool ng = (q0 < 0.0f) && (a0 > NEG_MIN);
            float cur = sp ? 1.0f : (ng ? -1.0f : 0.0f);
            a0 += sp ? 1 : (ng ? -1 : 0);
            q0 -= cur;
            ov.x = sp ? qth : (ng ? -qth : 0.0f);
        }
        // element 1
        {
            q1 += xv.y / qth;
            bool sp = (q1 - 1.0f >= 0.0f) && (a1 < POS_MAX);
            bool ng = (q1 < 0.0f) && (a1 > NEG_MIN);
            float cur = sp ? 1.0f : (ng ? -1.0f : 0.0f);
            a1 += sp ? 1 : (ng ? -1 : 0);
            q1 -= cur;
            ov.y = sp ? qth : (ng ? -qth : 0.0f);
        }
        // element 2
        {
            q2 += xv.z / qth;
            bool sp = (q2 - 1.0f >= 0.0f) && (a2 < POS_MAX);
            bool ng = (q2 < 0.0f) && (a2 > NEG_MIN);
            float cur = sp ? 1.0f : (ng ? -1.0f : 0.0f);
            a2 += sp ? 1 : (ng ? -1 : 0);
            q2 -= cur;
            ov.z = sp ? qth : (ng ? -qth : 0.0f);
        }
        // element 3
        {
            q3 += xv.w / qth;
            bool sp = (q3 - 1.0f >= 0.0f) && (a3 < POS_MAX);
            bool ng = (q3 < 0.0f) && (a3 > NEG_MIN);
            float cur = sp ? 1.0f : (ng ? -1.0f : 0.0f);
            a3 += sp ? 1 : (ng ? -1 : 0);
            q3 -= cur;
            ov.w = sp ? qth : (ng ? -qth : 0.0f);
        }

        *reinterpret_cast<float4*>(out + (size_t)t * S + idx) = ov;
    }
}

extern "C" void kernel_launch(void* const* d_in, const int* in_sizes, int n_in,
                              void* d_out, int out_size)
{
    const float* x   = (const float*)d_in[0];
    const float* qth = (const float*)d_in[1];
    float* out       = (float*)d_out;

    int total = in_sizes[0];          // T * S
    int S = total / T_STEPS;          // spatial size = 9,633,792
    int nthreads = S / 4;             // float4 per thread
    int block = 256;
    int grid = (nthreads + block - 1) / block;

    ifneuron_kernel<<<grid, block>>>(x, qth, out, S);
}

// round 2
// speedup vs baseline: 1.0916x; 1.0916x over previous
#include <cuda_runtime.h>

// ST-BIF IF neuron, T=16 scan. 8 spatial elements per thread (2x float4),
// state in registers, reciprocal-multiply instead of div, streaming ld/st.

#define T_STEPS 16
#define POS_MAX 7
#define NEG_MIN (-8)

__device__ __forceinline__ float step_elem(float xin, float rcp, float qth,
                                           float& q, int& a)
{
    q += xin * rcp;                  // qth = 0.5 -> exact (rcp = 2.0)
    bool sp = (q - 1.0f >= 0.0f) && (a < POS_MAX);
    bool ng = (q < 0.0f) && (a > NEG_MIN);
    a += sp ? 1 : (ng ? -1 : 0);
    q -= sp ? 1.0f : (ng ? -1.0f : 0.0f);
    return sp ? qth : (ng ? -qth : 0.0f);
}

__global__ void __launch_bounds__(256) ifneuron_kernel(
    const float* __restrict__ x,
    const float* __restrict__ qth_ptr,
    float* __restrict__ out,
    int S)   // spatial size (B*N*D), multiple of 8
{
    int idx = (blockIdx.x * blockDim.x + threadIdx.x) * 8;
    if (idx >= S) return;

    const float qth = __ldg(qth_ptr);
    const float rcp = 1.0f / qth;

    float q[8];
    int   a[8];
    #pragma unroll
    for (int i = 0; i < 8; i++) { q[i] = 0.5f; a[i] = 0; }

    #pragma unroll
    for (int t = 0; t < T_STEPS; t++) {
        const float* xp = x + (size_t)t * S + idx;
        float4 xa = __ldcs(reinterpret_cast<const float4*>(xp));
        float4 xb = __ldcs(reinterpret_cast<const float4*>(xp + 4));

        float4 oa, ob;
        oa.x = step_elem(xa.x, rcp, qth, q[0], a[0]);
        oa.y = step_elem(xa.y, rcp, qth, q[1], a[1]);
        oa.z = step_elem(xa.z, rcp, qth, q[2], a[2]);
        oa.w = step_elem(xa.w, rcp, qth, q[3], a[3]);
        ob.x = step_elem(xb.x, rcp, qth, q[4], a[4]);
        ob.y = step_elem(xb.y, rcp, qth, q[5], a[5]);
        ob.z = step_elem(xb.z, rcp, qth, q[6], a[6]);
        ob.w = step_elem(xb.w, rcp, qth, q[7], a[7]);

        float* op = out + (size_t)t * S + idx;
        __stcs(reinterpret_cast<float4*>(op), oa);
        __stcs(reinterpret_cast<float4*>(op + 4), ob);
    }
}

extern "C" void kernel_launch(void* const* d_in, const int* in_sizes, int n_in,
                              void* d_out, int out_size)
{
    const float* x   = (const float*)d_in[0];
    const float* qth = (const float*)d_in[1];
    float* out       = (float*)d_out;

    int total = in_sizes[0];          // T * S
    int S = total / T_STEPS;          // 9,633,792
    int nthreads = S / 8;             // 8 elems per thread
    int block = 256;
    int grid = (nthreads + block - 1) / block;

    ifneuron_kernel<<<grid, block>>>(x, qth, out, S);
}